// round 9
// baseline (speedup 1.0000x reference)
#include <cuda_runtime.h>
#include <cuda_bf16.h>

// ---------------------------------------------------------------------------
// Problem constants
// ---------------------------------------------------------------------------
namespace {
constexpr int NB  = 4096;    // batch
constexpr int NN  = 30;      // nodes
constexpr int INC = 512;     // input channels
constexpr int NF  = 128;     // hidden features
constexpr int NC  = 9;       // output channels
constexpr int BPB = 4;       // batches per block in kernel B (120 rows)
constexpr int MROWS = NB * NN;          // 122880

// kernel B dynamic smem layout (bytes)
constexpr int BOFF_CH  = 0;             // bf16[128][136]  XW/H1/G hi
constexpr int BOFF_CL  = 34816;         // lo
constexpr int BOFF_ANH = 69632;         // bf16[4][32][36]
constexpr int BOFF_ANL = 78848;
constexpr int BOFF_TMP = 88064;         // float[4][900] adjacency pattern
constexpr int BOFF_SDI = 102464;        // float[120]
constexpr int BOFF_SXP = 102944;        // float[2][120]
constexpr int BOFF_SX  = 103904;        // float[120]
constexpr int SMEM_B   = 104384;
}

// ---------------------------------------------------------------------------
// Global scratch (allocation forbidden)
// ---------------------------------------------------------------------------
__device__ uint2 g_XWf[(size_t)MROWS * 64];   // XW pre-split: {bf16x2 hi, bf16x2 lo} per col-pair
__device__ uint2 g_W1f[256 * 128];            // W1 mma B-fragments {hi,lo}
__device__ uint2 g_W2f[64 * 128];             // W2 mma B-fragments {hi,lo}

// ---------------------------------------------------------------------------
// Helpers
// ---------------------------------------------------------------------------
__device__ __forceinline__ unsigned smem_u32(const void* p) {
    unsigned a;
    asm("{ .reg .u64 t; cvta.to.shared.u64 t, %1; cvt.u32.u64 %0, t; }"
        : "=r"(a) : "l"(p));
    return a;
}

__device__ __forceinline__ void mma16816(float* c, const unsigned* a, const unsigned* b) {
    asm volatile(
        "mma.sync.aligned.m16n8k16.row.col.f32.bf16.bf16.f32 "
        "{%0,%1,%2,%3}, {%4,%5,%6,%7}, {%8,%9}, {%0,%1,%2,%3};\n"
        : "+f"(c[0]), "+f"(c[1]), "+f"(c[2]), "+f"(c[3])
        : "r"(a[0]), "r"(a[1]), "r"(a[2]), "r"(a[3]),
          "r"(b[0]), "r"(b[1]));
}

__device__ __forceinline__ void ldsm4(unsigned* r, unsigned addr) {
    asm volatile("ldmatrix.sync.aligned.m8n8.x4.shared.b16 {%0,%1,%2,%3}, [%4];"
                 : "=r"(r[0]), "=r"(r[1]), "=r"(r[2]), "=r"(r[3]) : "r"(addr));
}

__device__ __forceinline__ void store_split4(__nv_bfloat16* hi, __nv_bfloat16* lo, float4 v) {
    __nv_bfloat16 hx = __float2bfloat16_rn(v.x);
    __nv_bfloat16 hy = __float2bfloat16_rn(v.y);
    __nv_bfloat16 hz = __float2bfloat16_rn(v.z);
    __nv_bfloat16 hw = __float2bfloat16_rn(v.w);
    *(__nv_bfloat162*)(hi)     = __halves2bfloat162(hx, hy);
    *(__nv_bfloat162*)(hi + 2) = __halves2bfloat162(hz, hw);
    *(__nv_bfloat162*)(lo)     = __floats2bfloat162_rn(v.x - __bfloat162float(hx),
                                                       v.y - __bfloat162float(hy));
    *(__nv_bfloat162*)(lo + 2) = __floats2bfloat162_rn(v.z - __bfloat162float(hz),
                                                       v.w - __bfloat162float(hw));
}

__device__ __forceinline__ void split_store2(__nv_bfloat16* hp, __nv_bfloat16* lp,
                                             float x, float y) {
    __nv_bfloat16 hx = __float2bfloat16_rn(x);
    __nv_bfloat16 hy = __float2bfloat16_rn(y);
    *(__nv_bfloat162*)hp = __halves2bfloat162(hx, hy);
    *(__nv_bfloat162*)lp = __floats2bfloat162_rn(x - __bfloat162float(hx),
                                                 y - __bfloat162float(hy));
}

__device__ __forceinline__ uint2 split_pack2(float x, float y) {
    __nv_bfloat16 hx = __float2bfloat16_rn(x);
    __nv_bfloat16 hy = __float2bfloat16_rn(y);
    __nv_bfloat162 h = __halves2bfloat162(hx, hy);
    __nv_bfloat162 l = __floats2bfloat162_rn(x - __bfloat162float(hx),
                                             y - __bfloat162float(hy));
    uint2 r;
    r.x = *(unsigned*)&h;
    r.y = *(unsigned*)&l;
    return r;
}

__device__ __forceinline__ unsigned pack2(const __nv_bfloat16* p0, const __nv_bfloat16* p1) {
    unsigned u0 = *(const unsigned short*)p0;
    unsigned u1 = *(const unsigned short*)p1;
    return u0 | (u1 << 16);
}

// Block-diagonal prop GEMM for one batch: C[32x128] = An[32x32] @ X[32x128],
// split-bf16 3-pass. Warp covers 64 N-cols (nhalf). Strides: An 36, X 136.
__device__ __forceinline__ void prop_mma(
    const __nv_bfloat16* __restrict__ anh, const __nv_bfloat16* __restrict__ anl,
    const __nv_bfloat16* __restrict__ xh,  const __nv_bfloat16* __restrict__ xl,
    int nhalf, int g, int tq, float pacc[2][8][4])
{
#pragma unroll
    for (int mt = 0; mt < 2; mt++)
#pragma unroll
        for (int nt = 0; nt < 8; nt++)
#pragma unroll
            for (int q = 0; q < 4; q++) pacc[mt][nt][q] = 0.f;

#pragma unroll
    for (int kk = 0; kk < 2; kk++) {
        const int kc = kk * 16 + 2 * tq;
        unsigned ah[2][4], al[2][4];
#pragma unroll
        for (int mt = 0; mt < 2; mt++) {
            const int r = mt * 16 + g;
            ah[mt][0] = *(const unsigned*)&anh[r * 36 + kc];
            ah[mt][1] = *(const unsigned*)&anh[(r + 8) * 36 + kc];
            ah[mt][2] = *(const unsigned*)&anh[r * 36 + kc + 8];
            ah[mt][3] = *(const unsigned*)&anh[(r + 8) * 36 + kc + 8];
            al[mt][0] = *(const unsigned*)&anl[r * 36 + kc];
            al[mt][1] = *(const unsigned*)&anl[(r + 8) * 36 + kc];
            al[mt][2] = *(const unsigned*)&anl[r * 36 + kc + 8];
            al[mt][3] = *(const unsigned*)&anl[(r + 8) * 36 + kc + 8];
        }
#pragma unroll
        for (int nt = 0; nt < 8; nt++) {
            const int n = nhalf * 64 + nt * 8 + g;
            unsigned bh[2], bl[2];
            bh[0] = pack2(&xh[kc * 136 + n],       &xh[(kc + 1) * 136 + n]);
            bh[1] = pack2(&xh[(kc + 8) * 136 + n], &xh[(kc + 9) * 136 + n]);
            bl[0] = pack2(&xl[kc * 136 + n],       &xl[(kc + 1) * 136 + n]);
            bl[1] = pack2(&xl[(kc + 8) * 136 + n], &xl[(kc + 9) * 136 + n]);
#pragma unroll
            for (int mt = 0; mt < 2; mt++) {
                mma16816(pacc[mt][nt], ah[mt], bh);
                mma16816(pacc[mt][nt], ah[mt], bl);
                mma16816(pacc[mt][nt], al[mt], bh);
            }
        }
    }
}

// ---------------------------------------------------------------------------
// Init: pack W1 / W2 into mma B-fragment layout {hi,lo}.
// g_Wf[k2*128+n] = { {W[2k2][n],W[2k2+1][n]}_hi , residual_lo }
// ---------------------------------------------------------------------------
__global__ void init_w1frag(const float* __restrict__ W1) {
    const int idx = blockIdx.x * blockDim.x + threadIdx.x;
    if (idx >= 256 * 128) return;
    const int k2 = idx >> 7, n = idx & 127;
    g_W1f[idx] = split_pack2(W1[(2 * k2) * NF + n], W1[(2 * k2 + 1) * NF + n]);
}
__global__ void init_w2frag(const float* __restrict__ W2) {
    const int idx = blockIdx.x * blockDim.x + threadIdx.x;
    if (idx >= 64 * 128) return;
    const int k2 = idx >> 7, n = idx & 127;
    g_W2f[idx] = split_pack2(W2[(2 * k2) * NF + n], W2[(2 * k2 + 1) * NF + n]);
}

// ---------------------------------------------------------------------------
// Kernel A: GEMM1  XW = real @ W1   (split-bf16 3-pass)
// 128x128 block tile, BK=16, 8 warps (2x4), warp tile 64x32. 2 CTAs/SM.
// A fragments via ldmatrix.x4 from ping-pong smem; B fragments via LDG.64
// from the pre-packed g_W1f table (L1/L2 resident, no smem staging).
// Output written pre-split as uint2 {hi2, lo2} per column pair.
// ---------------------------------------------------------------------------
__global__ void __launch_bounds__(256, 2) gemm1_kernel(const float* __restrict__ A) {
    __shared__ __align__(16) __nv_bfloat16 sA[2][2][128][24];  // [buf][hi/lo]

    const int tid  = threadIdx.x;
    const int warp = tid >> 5, lane = tid & 31;
    const int wm = warp >> 2, wn = warp & 3;
    const int g  = lane >> 2, tq = lane & 3;
    const long mbase = (long)blockIdx.x * 128;

    float acc[4][4][4];
#pragma unroll
    for (int a = 0; a < 4; a++)
#pragma unroll
        for (int b = 0; b < 4; b++)
#pragma unroll
            for (int c = 0; c < 4; c++) acc[a][b][c] = 0.f;

    // A staging assignment
    const int rA0 = tid >> 2;            // 0..63 (and +64)
    const int kA0 = (tid & 3) * 4;
    const float* Ap0 = A + (mbase + rA0) * INC + kA0;
    const float* Ap1 = Ap0 + (long)64 * INC;

    // ldmatrix per-lane address component
    const int sel  = lane >> 3;                       // matrix index 0..3
    const int rowo = (sel & 1) * 8 + (lane & 7);      // row within 16-row tile
    const unsigned kb = (unsigned)(sel >> 1) * 16;    // k byte offset (0/16)
    const unsigned sbase = smem_u32(&sA[0][0][0][0]);
    const unsigned aoff  = (unsigned)(wm * 64 + rowo) * 48 + kb;
    // strides: buf=12288B, hi->lo=6144B, row=48B, mt tile=768B

    float4 ra = *(const float4*)Ap0;
    float4 rb = *(const float4*)Ap1;
    store_split4(&sA[0][0][rA0][kA0],      &sA[0][1][rA0][kA0],      ra);
    store_split4(&sA[0][0][rA0 + 64][kA0], &sA[0][1][rA0 + 64][kA0], rb);
    __syncthreads();

    constexpr int ITERS = INC / 16;      // 32
    for (int it = 0; it < ITERS; ++it) {
        const int cur = it & 1;
        if (it + 1 < ITERS) {            // prefetch next A slab
            ra = *(const float4*)(Ap0 + (it + 1) * 16);
            rb = *(const float4*)(Ap1 + (it + 1) * 16);
        }

        // B fragments straight from pre-packed table
        unsigned bh[4][2], blx[4][2];
        {
            const int k2 = it * 8 + tq;
#pragma unroll
            for (int nt = 0; nt < 4; nt++) {
                const int n = wn * 32 + nt * 8 + g;
                uint2 f0 = __ldg(&g_W1f[k2 * 128 + n]);
                uint2 f1 = __ldg(&g_W1f[(k2 + 4) * 128 + n]);
                bh[nt][0] = f0.x; blx[nt][0] = f0.y;
                bh[nt][1] = f1.x; blx[nt][1] = f1.y;
            }
        }

        const unsigned abase = sbase + (unsigned)cur * 12288u + aoff;
#pragma unroll
        for (int mt = 0; mt < 4; mt++) {
            unsigned ah[4], al[4];
            ldsm4(ah, abase + (unsigned)mt * 768u);
            ldsm4(al, abase + 6144u + (unsigned)mt * 768u);
#pragma unroll
            for (int nt = 0; nt < 4; nt++) {
                mma16816(acc[mt][nt], ah, bh[nt]);
                mma16816(acc[mt][nt], ah, blx[nt]);
                mma16816(acc[mt][nt], al, bh[nt]);
            }
        }

        if (it + 1 < ITERS) {
            const int nxt = cur ^ 1;
            store_split4(&sA[nxt][0][rA0][kA0],      &sA[nxt][1][rA0][kA0],      ra);
            store_split4(&sA[nxt][0][rA0 + 64][kA0], &sA[nxt][1][rA0 + 64][kA0], rb);
        }
        __syncthreads();
    }

    // epilogue: pre-split store (uint2 per col pair)
#pragma unroll
    for (int mt = 0; mt < 4; mt++) {
        const long row = mbase + wm * 64 + mt * 16 + g;
#pragma unroll
        for (int nt = 0; nt < 4; nt++) {
            const int c2 = wn * 16 + nt * 4 + tq;
            g_XWf[row * 64 + c2]       = split_pack2(acc[mt][nt][0], acc[mt][nt][1]);
            g_XWf[(row + 8) * 64 + c2] = split_pack2(acc[mt][nt][2], acc[mt][nt][3]);
        }
    }
}

// ---------------------------------------------------------------------------
// Kernel B: fused rest.  One block = 4 batches (120 rows -> 128 tile).
// ---------------------------------------------------------------------------
__global__ void __launch_bounds__(256, 2) fusedB_kernel(
    const float* __restrict__ graph,
    const float* __restrict__ b1,    const float* __restrict__ b2,
    const float* __restrict__ Wlin,  const float* __restrict__ blin,
    const float* __restrict__ Wconv, const float* __restrict__ bconv,
    float* __restrict__ out)
{
    extern __shared__ __align__(16) char smem[];
    __nv_bfloat16* ch  = (__nv_bfloat16*)(smem + BOFF_CH);
    __nv_bfloat16* cl  = (__nv_bfloat16*)(smem + BOFF_CL);
    __nv_bfloat16* anh = (__nv_bfloat16*)(smem + BOFF_ANH);
    __nv_bfloat16* anl = (__nv_bfloat16*)(smem + BOFF_ANL);
    float*         tmpS= (float*)(smem + BOFF_TMP);
    float*         sdi = (float*)(smem + BOFF_SDI);
    float*         sxp = (float*)(smem + BOFF_SXP);
    float*         sx  = (float*)(smem + BOFF_SX);

    const int tid  = threadIdx.x;
    const int warp = tid >> 5, lane = tid & 31;
    const int wm = warp >> 2, wn = warp & 3;        // GEMM2 warp grid
    const int bq = warp >> 1, nhalf = warp & 1;     // prop warp mapping
    const int g  = lane >> 2, tq = lane & 3;
    const int b0 = blockIdx.x * BPB;
    const long rowbase = (long)b0 * NN;

    // ---- stage XW (already split), zero pads, adjacency pattern ----
    for (int idx = tid; idx < 120 * 64; idx += 256) {
        const int r = idx >> 6, c2 = idx & 63;
        uint2 v = g_XWf[(rowbase + r) * 64 + c2];
        *(unsigned*)&ch[r * 136 + 2 * c2] = v.x;
        *(unsigned*)&cl[r * 136 + 2 * c2] = v.y;
    }
    {
        const __nv_bfloat16 z = __float2bfloat16_rn(0.f);
        for (int idx = tid; idx < 8 * 136; idx += 256) {       // rows 120..127
            ch[120 * 136 + idx] = z; cl[120 * 136 + idx] = z;
        }
        for (int idx = tid; idx < BPB * 32 * 36; idx += 256) { // An pad
            anh[idx] = z; anl[idx] = z;
        }
    }
    for (int idx = tid; idx < BPB * 900; idx += 256) {         // adjacency pattern
        const int b = idx / 900, rem = idx - b * 900;
        const float* gb = graph + ((size_t)(b0 + b) * 5) * 900 + rem;
        const float s = gb[0] + gb[900] + gb[1800] + gb[2700] + gb[3600];
        const int i = rem / 30, j = rem - i * 30;
        tmpS[idx] = (s != 0.0f || i == j) ? 1.0f : 0.0f;
    }
    __syncthreads();

    if (tid < BPB * NN) {                                       // dinv
        const int b = tid / NN, i = tid - b * NN;
        const float* rowp = tmpS + b * 900 + i * 30;
        float d = 0.f;
#pragma unroll
        for (int j = 0; j < NN; j++) d += rowp[j];
        sdi[tid] = rsqrtf(d);
    }
    __syncthreads();

    for (int idx = tid; idx < BPB * 900; idx += 256) {          // An -> hi/lo
        const int b = idx / 900, rem = idx - b * 900;
        const int i = rem / 30, j = rem - i * 30;
        const float v = sdi[b * 30 + i] * tmpS[idx] * sdi[b * 30 + j];
        const __nv_bfloat16 h = __float2bfloat16_rn(v);
        anh[(b * 32 + i) * 36 + j] = h;
        anl[(b * 32 + i) * 36 + j] = __float2bfloat16_rn(v - __bfloat162float(h));
    }
    __syncthreads();

    // ---- prop1: H1 = relu(An @ XW + b1) ----
    {
        float pacc[2][8][4];
        prop_mma(anh + bq * 32 * 36, anl + bq * 32 * 36,
                 ch + bq * 30 * 136, cl + bq * 30 * 136, nhalf, g, tq, pacc);
        __syncthreads();    // all XW reads done before overwrite
#pragma unroll
        for (int mt = 0; mt < 2; mt++) {
#pragma unroll
            for (int nt = 0; nt < 8; nt++) {
                const int n = nhalf * 64 + nt * 8 + 2 * tq;
                const float bx = __ldg(b1 + n), by = __ldg(b1 + n + 1);
                const int i0 = mt * 16 + g;
                if (i0 < NN)
                    split_store2(&ch[(bq * 30 + i0) * 136 + n], &cl[(bq * 30 + i0) * 136 + n],
                                 fmaxf(pacc[mt][nt][0] + bx, 0.f),
                                 fmaxf(pacc[mt][nt][1] + by, 0.f));
                const int i1 = i0 + 8;
                if (i1 < NN)
                    split_store2(&ch[(bq * 30 + i1) * 136 + n], &cl[(bq * 30 + i1) * 136 + n],
                                 fmaxf(pacc[mt][nt][2] + bx, 0.f),
                                 fmaxf(pacc[mt][nt][3] + by, 0.f));
            }
        }
        __syncthreads();
    }

    // ---- GEMM2: G = H1 @ W2 (A via ldmatrix, B via pre-packed table) ----
    float acc[4][4][4];
#pragma unroll
    for (int a = 0; a < 4; a++)
#pragma unroll
        for (int b = 0; b < 4; b++)
#pragma unroll
            for (int c = 0; c < 4; c++) acc[a][b][c] = 0.f;

    const int sel  = lane >> 3;
    const int rowo = (sel & 1) * 8 + (lane & 7);
    const unsigned kb = (unsigned)(sel >> 1) * 16;
    const unsigned chb = smem_u32(ch);
    const unsigned aoff2 = (unsigned)(wm * 64 + rowo) * 272 + kb;
    // strides: row=272B, mt tile=4352B, hi->lo=+34816B, k slab=+32B

#pragma unroll
    for (int it = 0; it < 8; ++it) {
        unsigned bh[4][2], blx[4][2];
        {
            const int k2 = it * 8 + tq;
#pragma unroll
            for (int nt = 0; nt < 4; nt++) {
                const int n = wn * 32 + nt * 8 + g;
                uint2 f0 = __ldg(&g_W2f[k2 * 128 + n]);
                uint2 f1 = __ldg(&g_W2f[(k2 + 4) * 128 + n]);
                bh[nt][0] = f0.x; blx[nt][0] = f0.y;
                bh[nt][1] = f1.x; blx[nt][1] = f1.y;
            }
        }
        const unsigned ab = chb + aoff2 + (unsigned)it * 32u;
#pragma unroll
        for (int mt = 0; mt < 4; mt++) {
            unsigned ah[4], al[4];
            ldsm4(ah, ab + (unsigned)mt * 4352u);
            ldsm4(al, ab + 34816u + (unsigned)mt * 4352u);
#pragma unroll
            for (int nt = 0; nt < 4; nt++) {
                mma16816(acc[mt][nt], ah, bh[nt]);
                mma16816(acc[mt][nt], ah, blx[nt]);
                mma16816(acc[mt][nt], al, bh[nt]);
            }
        }
    }
    __syncthreads();    // all H1 reads done

    // store G (split) straight from accumulators into ch/cl
#pragma unroll
    for (int mt = 0; mt < 4; mt++) {
        const int row = wm * 64 + mt * 16 + g;
#pragma unroll
        for (int nt = 0; nt < 4; nt++) {
            const int col = wn * 32 + nt * 8 + 2 * tq;
            split_store2(&ch[row * 136 + col],       &cl[row * 136 + col],
                         acc[mt][nt][0], acc[mt][nt][1]);
            split_store2(&ch[(row + 8) * 136 + col], &cl[(row + 8) * 136 + col],
                         acc[mt][nt][2], acc[mt][nt][3]);
        }
    }
    __syncthreads();

    // ---- prop2 + fused Wlin reduction:  x = relu( relu(An@G + b2) @ Wlin + blin )
    {
        float pacc[2][8][4];
        prop_mma(anh + bq * 32 * 36, anl + bq * 32 * 36,
                 ch + bq * 30 * 136, cl + bq * 30 * 136, nhalf, g, tq, pacc);

        float px[4] = {0.f, 0.f, 0.f, 0.f};  // rows g, g+8, g+16, g+24 partials
#pragma unroll
        for (int mt = 0; mt < 2; mt++) {
#pragma unroll
            for (int nt = 0; nt < 8; nt++) {
                const int n = nhalf * 64 + nt * 8 + 2 * tq;
                const float bx  = __ldg(b2 + n),   by  = __ldg(b2 + n + 1);
                const float wlx = __ldg(Wlin + n), wly = __ldg(Wlin + n + 1);
                px[mt * 2 + 0] += fmaxf(pacc[mt][nt][0] + bx, 0.f) * wlx
                                + fmaxf(pacc[mt][nt][1] + by, 0.f) * wly;
                px[mt * 2 + 1] += fmaxf(pacc[mt][nt][2] + bx, 0.f) * wlx
                                + fmaxf(pacc[mt][nt][3] + by, 0.f) * wly;
            }
        }
#pragma unroll
        for (int k = 0; k < 4; k++) {   // reduce over tq (lanes 4g..4g+3)
            px[k] += __shfl_xor_sync(0xffffffffu, px[k], 1);
            px[k] += __shfl_xor_sync(0xffffffffu, px[k], 2);
        }
        if (tq == 0) {
#pragma unroll
            for (int k = 0; k < 4; k++) {
                const int row = (k >> 1) * 16 + (k & 1) * 8 + g;
                if (row < NN) sxp[nhalf * 120 + bq * 30 + row] = px[k];
            }
        }
        __syncthreads();
    }

    if (tid < BPB * NN)
        sx[tid] = fmaxf(sxp[tid] + sxp[120 + tid] + __ldg(blin), 0.f);
    __syncthreads();

    // ---- head: out = x @ Wconv^T + bconv ----
    if (tid < BPB * NC) {
        const int b = tid / NC, c = tid - b * NC;
        float a = __ldg(bconv + c);
#pragma unroll
        for (int i = 0; i < NN; i++) a += sx[b * 30 + i] * __ldg(Wconv + c * 30 + i);
        out[(size_t)(b0 + b) * NC + c] = a;
    }
}

// ---------------------------------------------------------------------------
// Launch
// ---------------------------------------------------------------------------
extern "C" void kernel_launch(void* const* d_in, const int* in_sizes, int n_in,
                              void* d_out, int out_size) {
    const float* real  = (const float*)d_in[0];
    // d_in[1] = imag (unused by the reference)
    const float* graph = (const float*)d_in[2];
    const float* W1    = (const float*)d_in[3];
    const float* b1    = (const float*)d_in[4];
    const float* W2    = (const float*)d_in[5];
    const float* b2    = (const float*)d_in[6];
    const float* Wlin  = (const float*)d_in[7];
    const float* blin  = (const float*)d_in[8];
    const float* Wconv = (const float*)d_in[9];
    const float* bconv = (const float*)d_in[10];
    float* out = (float*)d_out;

    cudaFuncSetAttribute(fusedB_kernel,
                         cudaFuncAttributeMaxDynamicSharedMemorySize, SMEM_B);

    init_w1frag<<<128, 256>>>(W1);
    init_w2frag<<<32, 256>>>(W2);
    gemm1_kernel<<<MROWS / 128, 256>>>(real);
    fusedB_kernel<<<NB / BPB, 256, SMEM_B>>>(graph, b1, b2, Wlin, blin,
                                             Wconv, bconv, out);
}

// round 14
// speedup vs baseline: 1.2213x; 1.2213x over previous
#include <cuda_runtime.h>
#include <cuda_bf16.h>
#include <cstdint>

// ---------------------------------------------------------------------------
// Problem constants
// ---------------------------------------------------------------------------
namespace {
constexpr int NB  = 4096;    // batch
constexpr int NN  = 30;      // nodes
constexpr int INC = 512;     // input channels
constexpr int NF  = 128;     // hidden features
constexpr int NC  = 9;       // output channels
constexpr int BPB = 4;       // batches per block in kernel B (120 rows)
constexpr int MROWS = NB * NN;          // 122880

// gemm1 smem layout (dynamic): A then B, each [2 buf][2 hi/lo][128][40] bf16
constexpr int G_AOFF   = 0;
constexpr int G_BOFF   = 40960;
constexpr int G_BUFSTR = 20480;     // one buf = 2*128*80
constexpr int G_HLSTR  = 10240;     // hi -> lo
constexpr int SMEM_G   = 81920;

constexpr int BK    = 32;
constexpr int NSLAB = INC / BK;     // 16

// kernel B dynamic smem layout (bytes)
constexpr int BOFF_CH  = 0;             // bf16[128][136]  XW/H1/G hi
constexpr int BOFF_CL  = 34816;         // lo
constexpr int BOFF_ANH = 69632;         // bf16[4][32][36]
constexpr int BOFF_ANL = 78848;
constexpr int BOFF_TMP = 88064;         // float[4][900] adjacency pattern
constexpr int BOFF_SDI = 102464;        // float[120]
constexpr int BOFF_SXP = 102944;        // float[2][120]
constexpr int BOFF_SX  = 103904;        // float[120]
constexpr int SMEM_B   = 104384;
}

// ---------------------------------------------------------------------------
// Global scratch (allocation forbidden)
// ---------------------------------------------------------------------------
__device__ uint2 g_XWf[(size_t)MROWS * 64];   // XW pre-split {hi2,lo2} per col pair
// W1 transposed slab images: [slab][hi/lo][128 n][32 k] bf16, compact (8KB each)
__device__ uint4 g_W1t[NSLAB * 2 * 512];
__device__ uint2 g_W2f[64 * 128];             // W2 mma B-fragments {hi,lo}

// ---------------------------------------------------------------------------
// Helpers
// ---------------------------------------------------------------------------
__device__ __forceinline__ unsigned smem_u32(const void* p) {
    unsigned a;
    asm("{ .reg .u64 t; cvta.to.shared.u64 t, %1; cvt.u32.u64 %0, t; }"
        : "=r"(a) : "l"(p));
    return a;
}

__device__ __forceinline__ void mma16816(float* c, const unsigned* a, const unsigned* b) {
    asm volatile(
        "mma.sync.aligned.m16n8k16.row.col.f32.bf16.bf16.f32 "
        "{%0,%1,%2,%3}, {%4,%5,%6,%7}, {%8,%9}, {%0,%1,%2,%3};\n"
        : "+f"(c[0]), "+f"(c[1]), "+f"(c[2]), "+f"(c[3])
        : "r"(a[0]), "r"(a[1]), "r"(a[2]), "r"(a[3]),
          "r"(b[0]), "r"(b[1]));
}

__device__ __forceinline__ void ldsm4(unsigned* r, unsigned addr) {
    asm volatile("ldmatrix.sync.aligned.m8n8.x4.shared.b16 {%0,%1,%2,%3}, [%4];"
                 : "=r"(r[0]), "=r"(r[1]), "=r"(r[2]), "=r"(r[3]) : "r"(addr));
}

__device__ __forceinline__ void cpasync16(unsigned dst, const void* src) {
    asm volatile("cp.async.ca.shared.global [%0], [%1], 16;\n"
                 :: "r"(dst), "l"(src));
}

__device__ __forceinline__ void split_store2(__nv_bfloat16* hp, __nv_bfloat16* lp,
                                             float x, float y) {
    __nv_bfloat16 hx = __float2bfloat16_rn(x);
    __nv_bfloat16 hy = __float2bfloat16_rn(y);
    *(__nv_bfloat162*)hp = __halves2bfloat162(hx, hy);
    *(__nv_bfloat162*)lp = __floats2bfloat162_rn(x - __bfloat162float(hx),
                                                 y - __bfloat162float(hy));
}

__device__ __forceinline__ uint2 split_pack2(float x, float y) {
    __nv_bfloat16 hx = __float2bfloat16_rn(x);
    __nv_bfloat16 hy = __float2bfloat16_rn(y);
    __nv_bfloat162 h = __halves2bfloat162(hx, hy);
    __nv_bfloat162 l = __floats2bfloat162_rn(x - __bfloat162float(hx),
                                             y - __bfloat162float(hy));
    uint2 r;
    r.x = *(unsigned*)&h;
    r.y = *(unsigned*)&l;
    return r;
}

// convert 8 consecutive fp32 -> uint4 hi + uint4 lo (bf16x2 packed)
__device__ __forceinline__ void cvt8(float4 v0, float4 v1, uint4& hi, uint4& lo) {
    __nv_bfloat16 h0 = __float2bfloat16_rn(v0.x), h1 = __float2bfloat16_rn(v0.y);
    __nv_bfloat16 h2 = __float2bfloat16_rn(v0.z), h3 = __float2bfloat16_rn(v0.w);
    __nv_bfloat16 h4 = __float2bfloat16_rn(v1.x), h5 = __float2bfloat16_rn(v1.y);
    __nv_bfloat16 h6 = __float2bfloat16_rn(v1.z), h7 = __float2bfloat16_rn(v1.w);
    __nv_bfloat162 p01 = __halves2bfloat162(h0, h1);
    __nv_bfloat162 p23 = __halves2bfloat162(h2, h3);
    __nv_bfloat162 p45 = __halves2bfloat162(h4, h5);
    __nv_bfloat162 p67 = __halves2bfloat162(h6, h7);
    hi = make_uint4(*(unsigned*)&p01, *(unsigned*)&p23,
                    *(unsigned*)&p45, *(unsigned*)&p67);
    __nv_bfloat162 l01 = __floats2bfloat162_rn(v0.x - __bfloat162float(h0),
                                               v0.y - __bfloat162float(h1));
    __nv_bfloat162 l23 = __floats2bfloat162_rn(v0.z - __bfloat162float(h2),
                                               v0.w - __bfloat162float(h3));
    __nv_bfloat162 l45 = __floats2bfloat162_rn(v1.x - __bfloat162float(h4),
                                               v1.y - __bfloat162float(h5));
    __nv_bfloat162 l67 = __floats2bfloat162_rn(v1.z - __bfloat162float(h6),
                                               v1.w - __bfloat162float(h7));
    lo = make_uint4(*(unsigned*)&l01, *(unsigned*)&l23,
                    *(unsigned*)&l45, *(unsigned*)&l67);
}

__device__ __forceinline__ unsigned pack2(const __nv_bfloat16* p0, const __nv_bfloat16* p1) {
    unsigned u0 = *(const unsigned short*)p0;
    unsigned u1 = *(const unsigned short*)p1;
    return u0 | (u1 << 16);
}

// Block-diagonal prop GEMM for one batch: C[32x128] = An[32x32] @ X[32x128].
__device__ __forceinline__ void prop_mma(
    const __nv_bfloat16* __restrict__ anh, const __nv_bfloat16* __restrict__ anl,
    const __nv_bfloat16* __restrict__ xh,  const __nv_bfloat16* __restrict__ xl,
    int nhalf, int g, int tq, float pacc[2][8][4])
{
#pragma unroll
    for (int mt = 0; mt < 2; mt++)
#pragma unroll
        for (int nt = 0; nt < 8; nt++)
#pragma unroll
            for (int q = 0; q < 4; q++) pacc[mt][nt][q] = 0.f;

#pragma unroll
    for (int kk = 0; kk < 2; kk++) {
        const int kc = kk * 16 + 2 * tq;
        unsigned ah[2][4], al[2][4];
#pragma unroll
        for (int mt = 0; mt < 2; mt++) {
            const int r = mt * 16 + g;
            ah[mt][0] = *(const unsigned*)&anh[r * 36 + kc];
            ah[mt][1] = *(const unsigned*)&anh[(r + 8) * 36 + kc];
            ah[mt][2] = *(const unsigned*)&anh[r * 36 + kc + 8];
            ah[mt][3] = *(const unsigned*)&anh[(r + 8) * 36 + kc + 8];
            al[mt][0] = *(const unsigned*)&anl[r * 36 + kc];
            al[mt][1] = *(const unsigned*)&anl[(r + 8) * 36 + kc];
            al[mt][2] = *(const unsigned*)&anl[r * 36 + kc + 8];
            al[mt][3] = *(const unsigned*)&anl[(r + 8) * 36 + kc + 8];
        }
#pragma unroll
        for (int nt = 0; nt < 8; nt++) {
            const int n = nhalf * 64 + nt * 8 + g;
            unsigned bh[2], bl[2];
            bh[0] = pack2(&xh[kc * 136 + n],       &xh[(kc + 1) * 136 + n]);
            bh[1] = pack2(&xh[(kc + 8) * 136 + n], &xh[(kc + 9) * 136 + n]);
            bl[0] = pack2(&xl[kc * 136 + n],       &xl[(kc + 1) * 136 + n]);
            bl[1] = pack2(&xl[(kc + 8) * 136 + n], &xl[(kc + 9) * 136 + n]);
#pragma unroll
            for (int mt = 0; mt < 2; mt++) {
                mma16816(pacc[mt][nt], ah[mt], bh);
                mma16816(pacc[mt][nt], ah[mt], bl);
                mma16816(pacc[mt][nt], al[mt], bh);
            }
        }
    }
}

// ---------------------------------------------------------------------------
// Init kernels
// ---------------------------------------------------------------------------
// W1 -> transposed slab images Bt[n][k] (compact [128][32] bf16), hi/lo.
__global__ void init_w1t(const float* __restrict__ W1) {
    const int idx = blockIdx.x * blockDim.x + threadIdx.x;   // 16*128*32 = 65536
    if (idx >= NSLAB * 128 * 32) return;
    const int s = idx >> 12, rem = idx & 4095;
    const int n = rem >> 5, k = rem & 31;
    const float v = W1[(s * 32 + k) * NF + n];
    __nv_bfloat16 h = __float2bfloat16_rn(v);
    __nv_bfloat16* ph = (__nv_bfloat16*)g_W1t;
    ph[(s * 2 + 0) * 4096 + n * 32 + k] = h;
    ph[(s * 2 + 1) * 4096 + n * 32 + k] =
        __float2bfloat16_rn(v - __bfloat162float(h));
}

__global__ void init_w2frag(const float* __restrict__ W2) {
    const int idx = blockIdx.x * blockDim.x + threadIdx.x;
    if (idx >= 64 * 128) return;
    const int k2 = idx >> 7, n = idx & 127;
    g_W2f[idx] = split_pack2(W2[(2 * k2) * NF + n], W2[(2 * k2 + 1) * NF + n]);
}

// ---------------------------------------------------------------------------
// Kernel A: GEMM1  XW = real @ W1  (split-bf16 3-pass, all-ldmatrix fragments)
// 128x128 block tile, BK=32, ping-pong smem, 8 warps (2x4), warp tile 64x32.
// A staged fp32->hi/lo via regs; B slabs cp.async'd from pre-transposed image.
// ---------------------------------------------------------------------------
__global__ void __launch_bounds__(256, 2) gemm1_kernel(const float* __restrict__ A) {
    extern __shared__ __align__(16) char smem[];
    const unsigned sbase = smem_u32(smem);
    const int tid  = threadIdx.x;
    const int warp = tid >> 5, lane = tid & 31;
    const int wm = warp >> 2, wn = warp & 3;
    const int g  = lane >> 2, tq = lane & 3;
    const long mbase = (long)blockIdx.x * 128;

    float acc[4][4][4];
#pragma unroll
    for (int a = 0; a < 4; a++)
#pragma unroll
        for (int b = 0; b < 4; b++)
#pragma unroll
            for (int c = 0; c < 4; c++) acc[a][b][c] = 0.f;

    // ---- staging assignments
    const int arow = tid >> 1;                 // 0..127
    const int ahalf = (tid & 1);               // k-half (16 fp32)
    const float* Ap = A + (mbase + arow) * INC + ahalf * 16;
    const unsigned adst = sbase + G_AOFF + (unsigned)arow * 80 + (unsigned)ahalf * 32;
    // B: chunks tid, tid+256 of 512 16B-chunks per hi/lo slab image
    const unsigned bdst0 = sbase + G_BOFF + (unsigned)(tid >> 2) * 80 + (unsigned)(tid & 3) * 16;
    const int t2 = tid + 256;
    const unsigned bdst1 = sbase + G_BOFF + (unsigned)(t2 >> 2) * 80 + (unsigned)(t2 & 3) * 16;

    // ---- ldmatrix lane addressing
    const int sel  = lane >> 3;
    const unsigned l7 = (unsigned)(lane & 7);
    // A (validated R9 mapping): row = wm*64 + (sel&1)*8 + l7, k-byte = (sel>>1)*16
    const unsigned aoffL = ((unsigned)(wm * 64) + (unsigned)(sel & 1) * 8 + l7) * 80
                         + (unsigned)(sel >> 1) * 16;
    // B: row = wn*32 + (sel>>1)*8 + l7 (+ ntp*16), k-byte = (sel&1)*16
    const unsigned boffL = ((unsigned)(wn * 32) + (unsigned)(sel >> 1) * 8 + l7) * 80
                         + (unsigned)(sel & 1) * 16;

    // ---- prologue: slab 0
    float4 av[4];
    {
        const float4* p = (const float4*)Ap;
        av[0] = p[0]; av[1] = p[1]; av[2] = p[2]; av[3] = p[3];
    }
    {
        const uint4* srcH = g_W1t + 0 * 512;
        const uint4* srcL = g_W1t + 1 * 512;
        cpasync16(bdst0, srcH + tid);
        cpasync16(bdst1, srcH + t2);
        cpasync16(bdst0 + G_HLSTR, srcL + tid);
        cpasync16(bdst1 + G_HLSTR, srcL + t2);
        asm volatile("cp.async.commit_group;\n");
    }
    {
        uint4 hi0, lo0, hi1, lo1;
        cvt8(av[0], av[1], hi0, lo0);
        cvt8(av[2], av[3], hi1, lo1);
        *(uint4*)(smem + adst - sbase) = hi0;
        *(uint4*)(smem + adst - sbase + 16) = hi1;
        *(uint4*)(smem + adst - sbase + G_HLSTR) = lo0;
        *(uint4*)(smem + adst - sbase + G_HLSTR + 16) = lo1;
    }
    asm volatile("cp.async.wait_group 0;\n" ::: "memory");
    __syncthreads();

    for (int s = 0; s < NSLAB; ++s) {
        const unsigned cur = (unsigned)(s & 1);
        const unsigned nxt = cur ^ 1u;

        if (s + 1 < NSLAB) {
            // prefetch next A slab into regs; kick off next B cp.async
            const float4* p = (const float4*)(Ap + (s + 1) * BK);
            av[0] = p[0]; av[1] = p[1]; av[2] = p[2]; av[3] = p[3];
            const uint4* srcH = g_W1t + (size_t)((s + 1) * 2 + 0) * 512;
            const uint4* srcL = g_W1t + (size_t)((s + 1) * 2 + 1) * 512;
            const unsigned bb = nxt * G_BUFSTR;
            cpasync16(bdst0 + bb, srcH + tid);
            cpasync16(bdst1 + bb, srcH + t2);
            cpasync16(bdst0 + bb + G_HLSTR, srcL + tid);
            cpasync16(bdst1 + bb + G_HLSTR, srcL + t2);
            asm volatile("cp.async.commit_group;\n");
        }

        // ---- compute on buf cur (two k16 steps)
        const unsigned abB = sbase + G_AOFF + cur * G_BUFSTR + aoffL;
        const unsigned bbB = sbase + G_BOFF + cur * G_BUFSTR + boffL;
#pragma unroll
        for (int it2 = 0; it2 < 2; ++it2) {
            const unsigned kB = (unsigned)it2 * 32u;
            unsigned bh[4][2], bl[4][2];
#pragma unroll
            for (int ntp = 0; ntp < 2; ntp++) {
                unsigned rh[4], rl[4];
                ldsm4(rh, bbB + (unsigned)ntp * 1280u + kB);
                ldsm4(rl, bbB + (unsigned)ntp * 1280u + kB + G_HLSTR);
                bh[ntp * 2 + 0][0] = rh[0]; bh[ntp * 2 + 0][1] = rh[1];
                bh[ntp * 2 + 1][0] = rh[2]; bh[ntp * 2 + 1][1] = rh[3];
                bl[ntp * 2 + 0][0] = rl[0]; bl[ntp * 2 + 0][1] = rl[1];
                bl[ntp * 2 + 1][0] = rl[2]; bl[ntp * 2 + 1][1] = rl[3];
            }
#pragma unroll
            for (int mt = 0; mt < 4; mt++) {
                unsigned ah[4], al[4];
                ldsm4(ah, abB + (unsigned)mt * 1280u + kB);
                ldsm4(al, abB + (unsigned)mt * 1280u + kB + G_HLSTR);
#pragma unroll
                for (int nt = 0; nt < 4; nt++) {
                    mma16816(acc[mt][nt], ah, bh[nt]);
                    mma16816(acc[mt][nt], ah, bl[nt]);
                    mma16816(acc[mt][nt], al, bh[nt]);
                }
            }
        }

        if (s + 1 < NSLAB) {
            // store next A slab (buf nxt)
            uint4 hi0, lo0, hi1, lo1;
            cvt8(av[0], av[1], hi0, lo0);
            cvt8(av[2], av[3], hi1, lo1);
            char* d = smem + (adst - sbase) + nxt * G_BUFSTR;
            *(uint4*)(d) = hi0;
            *(uint4*)(d + 16) = hi1;
            *(uint4*)(d + G_HLSTR) = lo0;
            *(uint4*)(d + G_HLSTR + 16) = lo1;
        }
        asm volatile("cp.async.wait_group 0;\n" ::: "memory");
        __syncthreads();
    }

    // ---- epilogue: pre-split store (uint2 per col pair)
#pragma unroll
    for (int mt = 0; mt < 4; mt++) {
        const long row = mbase + wm * 64 + mt * 16 + g;
#pragma unroll
        for (int nt = 0; nt < 4; nt++) {
            const int c2 = wn * 16 + nt * 4 + tq;
            g_XWf[row * 64 + c2]       = split_pack2(acc[mt][nt][0], acc[mt][nt][1]);
            g_XWf[(row + 8) * 64 + c2] = split_pack2(acc[mt][nt][2], acc[mt][nt][3]);
        }
    }
}

// ---------------------------------------------------------------------------
// Kernel B: fused rest (R9-verified version, unchanged).
// ---------------------------------------------------------------------------
__global__ void __launch_bounds__(256, 2) fusedB_kernel(
    const float* __restrict__ graph,
    const float* __restrict__ b1,    const float* __restrict__ b2,
    const float* __restrict__ Wlin,  const float* __restrict__ blin,
    const float* __restrict__ Wconv, const float* __restrict__ bconv,
    float* __restrict__ out)
{
    extern __shared__ __align__(16) char smem[];
    __nv_bfloat16* ch  = (__nv_bfloat16*)(smem + BOFF_CH);
    __nv_bfloat16* cl  = (__nv_bfloat16*)(smem + BOFF_CL);
    __nv_bfloat16* anh = (__nv_bfloat16*)(smem + BOFF_ANH);
    __nv_bfloat16* anl = (__nv_bfloat16*)(smem + BOFF_ANL);
    float*         tmpS= (float*)(smem + BOFF_TMP);
    float*         sdi = (float*)(smem + BOFF_SDI);
    float*         sxp = (float*)(smem + BOFF_SXP);
    float*         sx  = (float*)(smem + BOFF_SX);

    const int tid  = threadIdx.x;
    const int warp = tid >> 5, lane = tid & 31;
    const int wm = warp >> 2, wn = warp & 3;        // GEMM2 warp grid
    const int bq = warp >> 1, nhalf = warp & 1;     // prop warp mapping
    const int g  = lane >> 2, tq = lane & 3;
    const int b0 = blockIdx.x * BPB;
    const long rowbase = (long)b0 * NN;

    // ---- stage XW (already split), zero pads, adjacency pattern ----
    for (int idx = tid; idx < 120 * 64; idx += 256) {
        const int r = idx >> 6, c2 = idx & 63;
        uint2 v = g_XWf[(rowbase + r) * 64 + c2];
        *(unsigned*)&ch[r * 136 + 2 * c2] = v.x;
        *(unsigned*)&cl[r * 136 + 2 * c2] = v.y;
    }
    {
        const __nv_bfloat16 z = __float2bfloat16_rn(0.f);
        for (int idx = tid; idx < 8 * 136; idx += 256) {       // rows 120..127
            ch[120 * 136 + idx] = z; cl[120 * 136 + idx] = z;
        }
        for (int idx = tid; idx < BPB * 32 * 36; idx += 256) { // An pad
            anh[idx] = z; anl[idx] = z;
        }
    }
    for (int idx = tid; idx < BPB * 900; idx += 256) {         // adjacency pattern
        const int b = idx / 900, rem = idx - b * 900;
        const float* gb = graph + ((size_t)(b0 + b) * 5) * 900 + rem;
        const float s = gb[0] + gb[900] + gb[1800] + gb[2700] + gb[3600];
        const int i = rem / 30, j = rem - i * 30;
        tmpS[idx] = (s != 0.0f || i == j) ? 1.0f : 0.0f;
    }
    __syncthreads();

    if (tid < BPB * NN) {                                       // dinv
        const int b = tid / NN, i = tid - b * NN;
        const float* rowp = tmpS + b * 900 + i * 30;
        float d = 0.f;
#pragma unroll
        for (int j = 0; j < NN; j++) d += rowp[j];
        sdi[tid] = rsqrtf(d);
    }
    __syncthreads();

    for (int idx = tid; idx < BPB * 900; idx += 256) {          // An -> hi/lo
        const int b = idx / 900, rem = idx - b * 900;
        const int i = rem / 30, j = rem - i * 30;
        const float v = sdi[b * 30 + i] * tmpS[idx] * sdi[b * 30 + j];
        const __nv_bfloat16 h = __float2bfloat16_rn(v);
        anh[(b * 32 + i) * 36 + j] = h;
        anl[(b * 32 + i) * 36 + j] = __float2bfloat16_rn(v - __bfloat162float(h));
    }
    __syncthreads();

    // ---- prop1: H1 = relu(An @ XW + b1) ----
    {
        float pacc[2][8][4];
        prop_mma(anh + bq * 32 * 36, anl + bq * 32 * 36,
                 ch + bq * 30 * 136, cl + bq * 30 * 136, nhalf, g, tq, pacc);
        __syncthreads();    // all XW reads done before overwrite
#pragma unroll
        for (int mt = 0; mt < 2; mt++) {
#pragma unroll
            for (int nt = 0; nt < 8; nt++) {
                const int n = nhalf * 64 + nt * 8 + 2 * tq;
                const float bx = __ldg(b1 + n), by = __ldg(b1 + n + 1);
                const int i0 = mt * 16 + g;
                if (i0 < NN)
                    split_store2(&ch[(bq * 30 + i0) * 136 + n], &cl[(bq * 30 + i0) * 136 + n],
                                 fmaxf(pacc[mt][nt][0] + bx, 0.f),
                                 fmaxf(pacc[mt][nt][1] + by, 0.f));
                const int i1 = i0 + 8;
                if (i1 < NN)
                    split_store2(&ch[(bq * 30 + i1) * 136 + n], &cl[(bq * 30 + i1) * 136 + n],
                                 fmaxf(pacc[mt][nt][2] + bx, 0.f),
                                 fmaxf(pacc[mt][nt][3] + by, 0.f));
            }
        }
        __syncthreads();
    }

    // ---- GEMM2: G = H1 @ W2 (A via ldmatrix, B via pre-packed table) ----
    float acc[4][4][4];
#pragma unroll
    for (int a = 0; a < 4; a++)
#pragma unroll
        for (int b = 0; b < 4; b++)
#pragma unroll
            for (int c = 0; c < 4; c++) acc[a][b][c] = 0.f;

    const int sel  = lane >> 3;
    const int rowo = (sel & 1) * 8 + (lane & 7);
    const unsigned kb = (unsigned)(sel >> 1) * 16;
    const unsigned chb = smem_u32(ch);
    const unsigned aoff2 = (unsigned)(wm * 64 + rowo) * 272 + kb;

#pragma unroll
    for (int it = 0; it < 8; ++it) {
        unsigned bh[4][2], blx[4][2];
        {
            const int k2 = it * 8 + tq;
#pragma unroll
            for (int nt = 0; nt < 4; nt++) {
                const int n = wn * 32 + nt * 8 + g;
                uint2 f0 = __ldg(&g_W2f[k2 * 128 + n]);
                uint2 f1 = __ldg(&g_W2f[(k2 + 4) * 128 + n]);
                bh[nt][0] = f0.x; blx[nt][0] = f0.y;
                bh[nt][1] = f1.x; blx[nt][1] = f1.y;
            }
        }
        const unsigned ab = chb + aoff2 + (unsigned)it * 32u;
#pragma unroll
        for (int mt = 0; mt < 4; mt++) {
            unsigned ah[4], al[4];
            ldsm4(ah, ab + (unsigned)mt * 4352u);
            ldsm4(al, ab + 34816u + (unsigned)mt * 4352u);
#pragma unroll
            for (int nt = 0; nt < 4; nt++) {
                mma16816(acc[mt][nt], ah, bh[nt]);
                mma16816(acc[mt][nt], ah, blx[nt]);
                mma16816(acc[mt][nt], al, bh[nt]);
            }
        }
    }
    __syncthreads();    // all H1 reads done

    // store G (split) straight from accumulators into ch/cl
#pragma unroll
    for (int mt = 0; mt < 4; mt++) {
        const int row = wm * 64 + mt * 16 + g;
#pragma unroll
        for (int nt = 0; nt < 4; nt++) {
            const int col = wn * 32 + nt * 8 + 2 * tq;
            split_store2(&ch[row * 136 + col],       &cl[row * 136 + col],
                         acc[mt][nt][0], acc[mt][nt][1]);
            split_store2(&ch[(row + 8) * 136 + col], &cl[(row + 8) * 136 + col],
                         acc[mt][nt][2], acc[mt][nt][3]);
        }
    }
    __syncthreads();

    // ---- prop2 + fused Wlin reduction ----
    {
        float pacc[2][8][4];
        prop_mma(anh + bq * 32 * 36, anl + bq * 32 * 36,
                 ch + bq * 30 * 136, cl + bq * 30 * 136, nhalf, g, tq, pacc);

        float px[4] = {0.f, 0.f, 0.f, 0.f};  // rows g, g+8, g+16, g+24 partials
#pragma unroll
        for (int mt = 0; mt < 2; mt++) {
#pragma unroll
            for (int nt = 0; nt < 8; nt++) {
                const int n = nhalf * 64 + nt * 8 + 2 * tq;
                const float bx  = __ldg(b2 + n),   by  = __ldg(b2 + n + 1);
                const float wlx = __ldg(Wlin + n), wly = __ldg(Wlin + n + 1);
                px[mt * 2 + 0] += fmaxf(pacc[mt][nt][0] + bx, 0.f) * wlx
                                + fmaxf(pacc[mt][nt][1] + by, 0.f) * wly;
                px[mt * 2 + 1] += fmaxf(pacc[mt][nt][2] + bx, 0.f) * wlx
                                + fmaxf(pacc[mt][nt][3] + by, 0.f) * wly;
            }
        }
#pragma unroll
        for (int k = 0; k < 4; k++) {   // reduce over tq (lanes 4g..4g+3)
            px[k] += __shfl_xor_sync(0xffffffffu, px[k], 1);
            px[k] += __shfl_xor_sync(0xffffffffu, px[k], 2);
        }
        if (tq == 0) {
#pragma unroll
            for (int k = 0; k < 4; k++) {
                const int row = (k >> 1) * 16 + (k & 1) * 8 + g;
                if (row < NN) sxp[nhalf * 120 + bq * 30 + row] = px[k];
            }
        }
        __syncthreads();
    }

    if (tid < BPB * NN)
        sx[tid] = fmaxf(sxp[tid] + sxp[120 + tid] + __ldg(blin), 0.f);
    __syncthreads();

    // ---- head: out = x @ Wconv^T + bconv ----
    if (tid < BPB * NC) {
        const int b = tid / NC, c = tid - b * NC;
        float a = __ldg(bconv + c);
#pragma unroll
        for (int i = 0; i < NN; i++) a += sx[b * 30 + i] * __ldg(Wconv + c * 30 + i);
        out[(size_t)(b0 + b) * NC + c] = a;
    }
}

// ---------------------------------------------------------------------------
// Launch
// ---------------------------------------------------------------------------
extern "C" void kernel_launch(void* const* d_in, const int* in_sizes, int n_in,
                              void* d_out, int out_size) {
    const float* real  = (const float*)d_in[0];
    // d_in[1] = imag (unused by the reference)
    const float* graph = (const float*)d_in[2];
    const float* W1    = (const float*)d_in[3];
    const float* b1    = (const float*)d_in[4];
    const float* W2    = (const float*)d_in[5];
    const float* b2    = (const float*)d_in[6];
    const float* Wlin  = (const float*)d_in[7];
    const float* blin  = (const float*)d_in[8];
    const float* Wconv = (const float*)d_in[9];
    const float* bconv = (const float*)d_in[10];
    float* out = (float*)d_out;

    cudaFuncSetAttribute(gemm1_kernel,
                         cudaFuncAttributeMaxDynamicSharedMemorySize, SMEM_G);
    cudaFuncSetAttribute(fusedB_kernel,
                         cudaFuncAttributeMaxDynamicSharedMemorySize, SMEM_B);

    init_w1t<<<256, 256>>>(W1);
    init_w2frag<<<32, 256>>>(W2);
    gemm1_kernel<<<MROWS / 128, 256, SMEM_G>>>(real);
    fusedB_kernel<<<NB / BPB, 256, SMEM_B>>>(graph, b1, b2, Wlin, blin,
                                             Wconv, bconv, out);
}